// round 10
// baseline (speedup 1.0000x reference)
#include <cuda_runtime.h>
#include <cuda_fp16.h>
#include <cstdint>

#define N_NODES 40000
#define N_EDGES 640000
#define F 128
#define SCALE_INV 0.08838834764831845f   // 1/sqrt(128)

#define NBLK 157            // ceil(40000/256) scan blocks

#define LDA 132
#define LDB 136
#define SMEM_BYTES ((128 * LDA + 128 * LDB) * 4)   // 137216 B

// ---- static scratch ----
// Interleaved K/H (fp16): per node, 32 groups of 8 halves (512 B per node):
//   [g*8+0..3] = K cols 4g..4g+3,  [g*8+4..7] = H cols 4g..4g+3
__device__ __half g_KH[N_NODES * 2 * F];
__device__ float  g_Q [N_NODES * F];     // (feat @ Wq) * (1/sqrt(F))  fp32
__device__ int    g_deg[N_NODES];        // stays zero between invocations
__device__ int    g_rowStart[N_NODES + 1];
__device__ int    g_rank[N_EDGES];       // edge's rank within its dst node
__device__ int    g_srcOff[N_EDGES];     // src node id << 9 (BYTE offset in g_KH)
__device__ int    g_bsum[NBLK];

// ---------------------------------------------------------------------------
// hist: count degrees AND record each edge's arrival rank (atomicAdd return).
__global__ void hist_kernel(const int* __restrict__ dst) {
    int base = (blockIdx.x * blockDim.x + threadIdx.x) << 2;   // 4 edges/thread
    if (base + 3 < N_EDGES) {
        int4 d = *(const int4*)(dst + base);
        int4 r;
        r.x = atomicAdd(&g_deg[d.x], 1);
        r.y = atomicAdd(&g_deg[d.y], 1);
        r.z = atomicAdd(&g_deg[d.z], 1);
        r.w = atomicAdd(&g_deg[d.w], 1);
        *(int4*)(g_rank + base) = r;
    } else {
        for (int e = base; e < N_EDGES; e++)
            g_rank[e] = atomicAdd(&g_deg[__ldg(&dst[e])], 1);
    }
}

// block-local exclusive scan of deg -> rowStart(local), block totals -> bsum.
// Zeroes g_deg after reading (invariant for next invocation).
__global__ __launch_bounds__(256) void scan1_kernel() {
    __shared__ int s[256];
    int tid = threadIdx.x;
    int i = blockIdx.x * 256 + tid;
    int v = 0;
    if (i < N_NODES) { v = g_deg[i]; g_deg[i] = 0; }
    s[tid] = v;
    __syncthreads();
#pragma unroll
    for (int off = 1; off < 256; off <<= 1) {
        int t = (tid >= off) ? s[tid - off] : 0;
        __syncthreads();
        s[tid] += t;
        __syncthreads();
    }
    if (i < N_NODES) g_rowStart[i] = s[tid] - v;
    if (tid == 255) g_bsum[blockIdx.x] = s[255];
}

// add block offsets (each block reduces bsum[t < blockIdx] itself); sentinel.
__global__ __launch_bounds__(256) void scan23_kernel() {
    __shared__ int red[256];
    int tid = threadIdx.x;
    int v = (tid < NBLK && tid < blockIdx.x) ? g_bsum[tid] : 0;
    red[tid] = v;
    __syncthreads();
#pragma unroll
    for (int off = 128; off > 0; off >>= 1) {
        if (tid < off) red[tid] += red[tid + off];
        __syncthreads();
    }
    int offset = red[0];

    int i = blockIdx.x * 256 + tid;
    if (i < N_NODES) g_rowStart[i] += offset;
    if (i == 0) g_rowStart[N_NODES] = N_EDGES;
}

// atomic-free scatter: slot = rowStart[dst] + rank[edge]
__global__ void scatter_kernel(const int* __restrict__ src,
                               const int* __restrict__ dst) {
    int base = (blockIdx.x * blockDim.x + threadIdx.x) << 2;   // 4 edges/thread
    if (base + 3 < N_EDGES) {
        int4 d = *(const int4*)(dst + base);
        int4 s = *(const int4*)(src + base);
        int4 r = *(const int4*)(g_rank + base);
        g_srcOff[g_rowStart[d.x] + r.x] = s.x << 9;
        g_srcOff[g_rowStart[d.y] + r.y] = s.y << 9;
        g_srcOff[g_rowStart[d.z] + r.z] = s.z << 9;
        g_srcOff[g_rowStart[d.w] + r.w] = s.w << 9;
    } else {
        for (int e = base; e < N_EDGES; e++) {
            int d = __ldg(&dst[e]);
            g_srcOff[g_rowStart[d] + g_rank[e]] = __ldg(&src[e]) << 9;
        }
    }
}

// ---------------------------------------------------------------------------
__device__ __forceinline__ uint32_t f2tf32(float x) {
    uint32_t r;
    asm("cvt.rna.tf32.f32 %0, %1;" : "=r"(r) : "f"(x));
    return r;
}

// Fused 3-way GEMM (tf32 tensor cores): one 128x128 row tile per CTA;
// A staged ONCE, the three weights staged sequentially into Bs.
// H (j=0) and K (j=2) write fp16 into the interleaved g_KH; Q (j=1) fp32,
// pre-scaled by 1/sqrt(F).
__global__ __launch_bounds__(256) void gemm3_tf32_kernel(
    const float* __restrict__ feat,
    const float* __restrict__ Wfc,
    const float* __restrict__ Wq,
    const float* __restrict__ Wk)
{
    extern __shared__ float sm[];
    float* As = sm;                 // [128][LDA]
    float* Bs = sm + 128 * LDA;     // [128][LDB]

    const int tid  = threadIdx.x;
    const int row0 = blockIdx.x * 128;

    for (int i = tid; i < 4096; i += 256) {
        int r = i >> 5, c4 = (i & 31) << 2;
        float4 v = make_float4(0.f, 0.f, 0.f, 0.f);
        if (row0 + r < N_NODES)
            v = *(const float4*)(feat + (size_t)(row0 + r) * F + c4);
        *(float4*)(As + r * LDA + c4) = v;
    }

    const int wid  = tid >> 5;
    const int lane = tid & 31;
    const int wm   = (wid & 3) << 5;
    const int wn   = (wid >> 2) << 6;
    const int grp  = lane >> 2;
    const int qid  = lane & 3;

    const float* Ws[3] = { Wfc, Wq, Wk };

#pragma unroll
    for (int j = 0; j < 3; j++) {
        __syncthreads();
        const float* W = Ws[j];
        for (int i = tid; i < 4096; i += 256) {
            int r = i >> 5, c4 = (i & 31) << 2;
            *(float4*)(Bs + r * LDB + c4) = *(const float4*)(W + r * F + c4);
        }
        __syncthreads();

        float acc[2][8][4];
#pragma unroll
        for (int mi = 0; mi < 2; mi++)
#pragma unroll
            for (int nt = 0; nt < 8; nt++)
#pragma unroll
                for (int c = 0; c < 4; c++) acc[mi][nt][c] = 0.0f;

#pragma unroll
        for (int ks = 0; ks < 16; ks++) {
            const int k0 = ks << 3;
            uint32_t a[2][4];
#pragma unroll
            for (int mi = 0; mi < 2; mi++) {
                const int rb = wm + (mi << 4);
                a[mi][0] = f2tf32(As[(rb + grp)     * LDA + k0 + qid]);
                a[mi][1] = f2tf32(As[(rb + grp + 8) * LDA + k0 + qid]);
                a[mi][2] = f2tf32(As[(rb + grp)     * LDA + k0 + qid + 4]);
                a[mi][3] = f2tf32(As[(rb + grp + 8) * LDA + k0 + qid + 4]);
            }
#pragma unroll
            for (int nt = 0; nt < 8; nt++) {
                const int n0 = wn + (nt << 3);
                uint32_t b0 = f2tf32(Bs[(k0 + qid)     * LDB + n0 + grp]);
                uint32_t b1 = f2tf32(Bs[(k0 + qid + 4) * LDB + n0 + grp]);
#pragma unroll
                for (int mi = 0; mi < 2; mi++) {
                    asm volatile(
                        "mma.sync.aligned.m16n8k8.row.col.f32.tf32.tf32.f32 "
                        "{%0,%1,%2,%3}, {%4,%5,%6,%7}, {%8,%9}, {%0,%1,%2,%3};"
                        : "+f"(acc[mi][nt][0]), "+f"(acc[mi][nt][1]),
                          "+f"(acc[mi][nt][2]), "+f"(acc[mi][nt][3])
                        : "r"(a[mi][0]), "r"(a[mi][1]), "r"(a[mi][2]),
                          "r"(a[mi][3]), "r"(b0), "r"(b1));
                }
            }
        }

        const int khOff = (j == 0) ? 4 : 0;   // H -> slot+4, K -> slot+0
#pragma unroll
        for (int mi = 0; mi < 2; mi++) {
            const int r = row0 + wm + (mi << 4) + grp;
#pragma unroll
            for (int nt = 0; nt < 8; nt++) {
                const int col = wn + (nt << 3) + (qid << 1);   // col even
                if (j == 1) {          // Q fp32, pre-scaled
                    if (r < N_NODES)
                        *(float2*)(g_Q + (size_t)r * F + col) =
                            make_float2(acc[mi][nt][0] * SCALE_INV,
                                        acc[mi][nt][1] * SCALE_INV);
                    if (r + 8 < N_NODES)
                        *(float2*)(g_Q + (size_t)(r + 8) * F + col) =
                            make_float2(acc[mi][nt][2] * SCALE_INV,
                                        acc[mi][nt][3] * SCALE_INV);
                } else {               // H/K fp16 interleaved
                    const int slot = ((col >> 2) << 3) + khOff + (col & 3);
                    if (r < N_NODES)
                        *(__half2*)(g_KH + (size_t)r * 256 + slot) =
                            __floats2half2_rn(acc[mi][nt][0], acc[mi][nt][1]);
                    if (r + 8 < N_NODES)
                        *(__half2*)(g_KH + (size_t)(r + 8) * 256 + slot) =
                            __floats2half2_rn(acc[mi][nt][2], acc[mi][nt][3]);
                }
            }
        }
    }
}

// ---------------------------------------------------------------------------
// Fused attention: TWO warps per dst node (each handles alternating 32-edge
// chunks), partials combined via smem. ILP-4 + partitioned warp reduction.
// ---------------------------------------------------------------------------
__device__ __forceinline__ void load_kh(unsigned off,
    float& kx, float& ky, float& kz, float& kw,
    float& hx, float& hy, float& hz, float& hw)
{
    uint4 raw = *(const uint4*)((const char*)g_KH + off);
    float2 f0 = __half22float2(*(__half2*)&raw.x);
    float2 f1 = __half22float2(*(__half2*)&raw.y);
    float2 f2 = __half22float2(*(__half2*)&raw.z);
    float2 f3 = __half22float2(*(__half2*)&raw.w);
    kx = f0.x; ky = f0.y; kz = f1.x; kw = f1.y;
    hx = f2.x; hy = f2.y; hz = f3.x; hw = f3.y;
}

__global__ __launch_bounds__(256) void fused_attn_kernel(float* __restrict__ out)
{
    __shared__ float4 sPart[8][32];
    __shared__ float  sDen[8];

    const int wib  = threadIdx.x >> 5;            // warp in block (0..7)
    const int lane = threadIdx.x & 31;
    const int gid  = blockIdx.x * 256 + threadIdx.x;
    const int gw   = gid >> 6;                    // node id (2 warps/node)
    const int half = (gid >> 5) & 1;              // which half-warp of the pair

    int beg = g_rowStart[gw];
    int end = g_rowStart[gw + 1];

    float4 q = *(const float4*)(g_Q + (unsigned)(gw * F + lane * 4));

    float ax = 0.f, ay = 0.f, az = 0.f, aw = 0.f;
    float den = 0.f;
    const unsigned lo = (unsigned)(lane << 4);    // byte offset in row
    const int g = lane >> 3;                      // lane group 0..3

    for (int chunk = beg + half * 32; chunk < end; chunk += 64) {
        int idx = chunk + lane;
        int myO = (idx < end) ? __ldg(&g_srcOff[idx]) : 0;
        int m = end - chunk; if (m > 32) m = 32;

        int j = 0;
        for (; j + 4 <= m; j += 4) {
            unsigned o0 = (unsigned)__shfl_sync(0xFFFFFFFFu, myO, j)     + lo;
            unsigned o1 = (unsigned)__shfl_sync(0xFFFFFFFFu, myO, j + 1) + lo;
            unsigned o2 = (unsigned)__shfl_sync(0xFFFFFFFFu, myO, j + 2) + lo;
            unsigned o3 = (unsigned)__shfl_sync(0xFFFFFFFFu, myO, j + 3) + lo;
            float k0x,k0y,k0z,k0w, h0x,h0y,h0z,h0w;
            float k1x,k1y,k1z,k1w, h1x,h1y,h1z,h1w;
            float k2x,k2y,k2z,k2w, h2x,h2y,h2z,h2w;
            float k3x,k3y,k3z,k3w, h3x,h3y,h3z,h3w;
            load_kh(o0, k0x,k0y,k0z,k0w, h0x,h0y,h0z,h0w);
            load_kh(o1, k1x,k1y,k1z,k1w, h1x,h1y,h1z,h1w);
            load_kh(o2, k2x,k2y,k2z,k2w, h2x,h2y,h2z,h2w);
            load_kh(o3, k3x,k3y,k3z,k3w, h3x,h3y,h3z,h3w);

            float v0 = q.x*k0x + q.y*k0y + q.z*k0z + q.w*k0w;
            float v1 = q.x*k1x + q.y*k1y + q.z*k1z + q.w*k1w;
            float v2 = q.x*k2x + q.y*k2y + q.z*k2z + q.w*k2w;
            float v3 = q.x*k3x + q.y*k3y + q.z*k3z + q.w*k3w;

            v0 += __shfl_xor_sync(0xFFFFFFFFu, v0, 16);
            v1 += __shfl_xor_sync(0xFFFFFFFFu, v1, 16);
            v2 += __shfl_xor_sync(0xFFFFFFFFu, v2, 16);
            v3 += __shfl_xor_sync(0xFFFFFFFFu, v3, 16);
            v0 += __shfl_xor_sync(0xFFFFFFFFu, v0, 8);
            v1 += __shfl_xor_sync(0xFFFFFFFFu, v1, 8);
            v2 += __shfl_xor_sync(0xFFFFFFFFu, v2, 8);
            v3 += __shfl_xor_sync(0xFFFFFFFFu, v3, 8);
            float x = v0;
            x = (g == 1) ? v1 : x;
            x = (g == 2) ? v2 : x;
            x = (g == 3) ? v3 : x;
            x += __shfl_xor_sync(0xFFFFFFFFu, x, 4);
            x += __shfl_xor_sync(0xFFFFFFFFu, x, 2);
            x += __shfl_xor_sync(0xFFFFFFFFu, x, 1);
            float y = __expf(x);
            float e0 = __shfl_sync(0xFFFFFFFFu, y, 0);
            float e1 = __shfl_sync(0xFFFFFFFFu, y, 8);
            float e2 = __shfl_sync(0xFFFFFFFFu, y, 16);
            float e3 = __shfl_sync(0xFFFFFFFFu, y, 24);

            den += (e0 + e1) + (e2 + e3);
            ax += e0*h0x + e1*h1x + e2*h2x + e3*h3x;
            ay += e0*h0y + e1*h1y + e2*h2y + e3*h3y;
            az += e0*h0z + e1*h1z + e2*h2z + e3*h3z;
            aw += e0*h0w + e1*h1w + e2*h2w + e3*h3w;
        }
        for (; j < m; j++) {
            unsigned o0 = (unsigned)__shfl_sync(0xFFFFFFFFu, myO, j) + lo;
            float kx,ky,kz,kw, hx,hy,hz,hw;
            load_kh(o0, kx,ky,kz,kw, hx,hy,hz,hw);
            float v0 = q.x*kx + q.y*ky + q.z*kz + q.w*kw;
#pragma unroll
            for (int o = 16; o > 0; o >>= 1)
                v0 += __shfl_xor_sync(0xFFFFFFFFu, v0, o);
            float e0 = __expf(v0);
            den += e0;
            ax += e0*hx; ay += e0*hy; az += e0*hz; aw += e0*hw;
        }
    }

    sPart[wib][lane] = make_float4(ax, ay, az, aw);
    if (lane == 0) sDen[wib] = den;
    __syncthreads();

    if (half == 0) {
        float4 p = sPart[wib + 1][lane];
        float dtot = den + sDen[wib + 1];
        float4 r;
        if (beg == end) {
            r = make_float4(0.f, 0.f, 0.f, 0.f);
        } else {
            float inv = 1.0f / dtot;
            r = make_float4((ax + p.x) * inv, (ay + p.y) * inv,
                            (az + p.z) * inv, (aw + p.w) * inv);
        }
        *(float4*)(out + (size_t)gw * F + lane * 4) = r;
    }
}

// ---------------------------------------------------------------------------
// Inputs: 0 feat, 1 loc, 2 W_fc, 3 Wq, 4 Wk, 5 Wq2, 6 Wk2, 7 G_w, 8 embed,
// 9 boundaries, 10 src, 11 dst, 12 inter_ids  (e2 branch is dead code)
// ---------------------------------------------------------------------------
extern "C" void kernel_launch(void* const* d_in, const int* in_sizes, int n_in,
                              void* d_out, int out_size)
{
    const float* feat = (const float*)d_in[0];
    const float* Wfc  = (const float*)d_in[2];
    const float* Wq   = (const float*)d_in[3];
    const float* Wk   = (const float*)d_in[4];
    const int*   src  = (const int*)d_in[10];
    const int*   dst  = (const int*)d_in[11];
    float* out = (float*)d_out;

    static cudaStream_t s2 = nullptr;
    static cudaEvent_t evFork = nullptr, evJoin = nullptr;
    if (!s2) {
        cudaFuncSetAttribute(gemm3_tf32_kernel,
                             cudaFuncAttributeMaxDynamicSharedMemorySize,
                             SMEM_BYTES);
        cudaStreamCreateWithFlags(&s2, cudaStreamNonBlocking);
        cudaEventCreateWithFlags(&evFork, cudaEventDisableTiming);
        cudaEventCreateWithFlags(&evJoin, cudaEventDisableTiming);
    }

    // fork: CSR build on s2, GEMM on the main (capture) stream
    cudaEventRecord(evFork, 0);
    cudaStreamWaitEvent(s2, evFork, 0);

    {   // --- s2: CSR build (rank-based, atomic-free scatter) ---
        int t4 = (N_EDGES + 3) / 4;
        hist_kernel<<<(t4 + 255) / 256, 256, 0, s2>>>(dst);
        scan1_kernel<<<NBLK, 256, 0, s2>>>();
        scan23_kernel<<<NBLK, 256, 0, s2>>>();
        scatter_kernel<<<(t4 + 255) / 256, 256, 0, s2>>>(src, dst);
        cudaEventRecord(evJoin, s2);
    }

    // --- main stream: H, Q, K GEMMs ---
    gemm3_tf32_kernel<<<(N_NODES + 127) / 128, 256, SMEM_BYTES>>>(
        feat, Wfc, Wq, Wk);

    // join, then fused attention (2 warps per node -> 10000 blocks)
    cudaStreamWaitEvent(0, evJoin, 0);
    fused_attn_kernel<<<(N_NODES * 64) / 256, 256>>>(out);
}

// round 11
// speedup vs baseline: 1.1424x; 1.1424x over previous
#include <cuda_runtime.h>
#include <cuda_fp16.h>
#include <cstdint>

#define N_NODES 40000
#define N_EDGES 640000
#define F 128
#define SCALE_INV 0.08838834764831845f   // 1/sqrt(128)

#define NBLK 157            // ceil(40000/256) scan blocks

#define LDA 132
#define LDB 136
#define SMEM_BYTES ((128 * LDA + 128 * LDB) * 4)   // 137216 B

// ---- static scratch ----
// Interleaved K/H (fp16): per node, 32 groups of 8 halves (512 B per node):
//   [g*8+0..3] = K cols 4g..4g+3,  [g*8+4..7] = H cols 4g..4g+3
__device__ __half g_KH[N_NODES * 2 * F];
__device__ float  g_Q [N_NODES * F];     // (feat @ Wq) * (1/sqrt(F))  fp32
__device__ int    g_deg[N_NODES];        // stays zero between invocations
__device__ int    g_rowStart[N_NODES + 1];
__device__ int    g_rank[N_EDGES];       // edge's rank within its dst node
__device__ int    g_srcOff[N_EDGES];     // src node id << 9 (BYTE offset in g_KH)
__device__ int    g_bsum[NBLK];

// ---------------------------------------------------------------------------
// hist: count degrees AND record each edge's arrival rank (atomicAdd return).
__global__ void hist_kernel(const int* __restrict__ dst) {
    int base = (blockIdx.x * blockDim.x + threadIdx.x) << 2;   // 4 edges/thread
    if (base + 3 < N_EDGES) {
        int4 d = *(const int4*)(dst + base);
        int4 r;
        r.x = atomicAdd(&g_deg[d.x], 1);
        r.y = atomicAdd(&g_deg[d.y], 1);
        r.z = atomicAdd(&g_deg[d.z], 1);
        r.w = atomicAdd(&g_deg[d.w], 1);
        *(int4*)(g_rank + base) = r;
    } else {
        for (int e = base; e < N_EDGES; e++)
            g_rank[e] = atomicAdd(&g_deg[__ldg(&dst[e])], 1);
    }
}

// block-local exclusive scan of deg -> rowStart(local), block totals -> bsum.
// Zeroes g_deg after reading (invariant for next invocation).
__global__ __launch_bounds__(256) void scan1_kernel() {
    __shared__ int s[256];
    int tid = threadIdx.x;
    int i = blockIdx.x * 256 + tid;
    int v = 0;
    if (i < N_NODES) { v = g_deg[i]; g_deg[i] = 0; }
    s[tid] = v;
    __syncthreads();
#pragma unroll
    for (int off = 1; off < 256; off <<= 1) {
        int t = (tid >= off) ? s[tid - off] : 0;
        __syncthreads();
        s[tid] += t;
        __syncthreads();
    }
    if (i < N_NODES) g_rowStart[i] = s[tid] - v;
    if (tid == 255) g_bsum[blockIdx.x] = s[255];
}

// add block offsets (each block reduces bsum[t < blockIdx] itself); sentinel.
__global__ __launch_bounds__(256) void scan23_kernel() {
    __shared__ int red[256];
    int tid = threadIdx.x;
    int v = (tid < NBLK && tid < blockIdx.x) ? g_bsum[tid] : 0;
    red[tid] = v;
    __syncthreads();
#pragma unroll
    for (int off = 128; off > 0; off >>= 1) {
        if (tid < off) red[tid] += red[tid + off];
        __syncthreads();
    }
    int offset = red[0];

    int i = blockIdx.x * 256 + tid;
    if (i < N_NODES) g_rowStart[i] += offset;
    if (i == 0) g_rowStart[N_NODES] = N_EDGES;
}

// atomic-free scatter: slot = rowStart[dst] + rank[edge]
__global__ void scatter_kernel(const int* __restrict__ src,
                               const int* __restrict__ dst) {
    int base = (blockIdx.x * blockDim.x + threadIdx.x) << 2;   // 4 edges/thread
    if (base + 3 < N_EDGES) {
        int4 d = *(const int4*)(dst + base);
        int4 s = *(const int4*)(src + base);
        int4 r = *(const int4*)(g_rank + base);
        g_srcOff[g_rowStart[d.x] + r.x] = s.x << 9;
        g_srcOff[g_rowStart[d.y] + r.y] = s.y << 9;
        g_srcOff[g_rowStart[d.z] + r.z] = s.z << 9;
        g_srcOff[g_rowStart[d.w] + r.w] = s.w << 9;
    } else {
        for (int e = base; e < N_EDGES; e++) {
            int d = __ldg(&dst[e]);
            g_srcOff[g_rowStart[d] + g_rank[e]] = __ldg(&src[e]) << 9;
        }
    }
}

// ---------------------------------------------------------------------------
__device__ __forceinline__ uint32_t f2tf32(float x) {
    uint32_t r;
    asm("cvt.rna.tf32.f32 %0, %1;" : "=r"(r) : "f"(x));
    return r;
}

// Fused 3-way GEMM (tf32 tensor cores): one 128x128 row tile per CTA;
// A staged ONCE, the three weights staged sequentially into Bs.
// H (j=0) and K (j=2) write fp16 into the interleaved g_KH; Q (j=1) fp32,
// pre-scaled by 1/sqrt(F).
__global__ __launch_bounds__(256) void gemm3_tf32_kernel(
    const float* __restrict__ feat,
    const float* __restrict__ Wfc,
    const float* __restrict__ Wq,
    const float* __restrict__ Wk)
{
    extern __shared__ float sm[];
    float* As = sm;                 // [128][LDA]
    float* Bs = sm + 128 * LDA;     // [128][LDB]

    const int tid  = threadIdx.x;
    const int row0 = blockIdx.x * 128;

    for (int i = tid; i < 4096; i += 256) {
        int r = i >> 5, c4 = (i & 31) << 2;
        float4 v = make_float4(0.f, 0.f, 0.f, 0.f);
        if (row0 + r < N_NODES)
            v = *(const float4*)(feat + (size_t)(row0 + r) * F + c4);
        *(float4*)(As + r * LDA + c4) = v;
    }

    const int wid  = tid >> 5;
    const int lane = tid & 31;
    const int wm   = (wid & 3) << 5;
    const int wn   = (wid >> 2) << 6;
    const int grp  = lane >> 2;
    const int qid  = lane & 3;

    const float* Ws[3] = { Wfc, Wq, Wk };

#pragma unroll
    for (int j = 0; j < 3; j++) {
        __syncthreads();
        const float* W = Ws[j];
        for (int i = tid; i < 4096; i += 256) {
            int r = i >> 5, c4 = (i & 31) << 2;
            *(float4*)(Bs + r * LDB + c4) = *(const float4*)(W + r * F + c4);
        }
        __syncthreads();

        float acc[2][8][4];
#pragma unroll
        for (int mi = 0; mi < 2; mi++)
#pragma unroll
            for (int nt = 0; nt < 8; nt++)
#pragma unroll
                for (int c = 0; c < 4; c++) acc[mi][nt][c] = 0.0f;

#pragma unroll
        for (int ks = 0; ks < 16; ks++) {
            const int k0 = ks << 3;
            uint32_t a[2][4];
#pragma unroll
            for (int mi = 0; mi < 2; mi++) {
                const int rb = wm + (mi << 4);
                a[mi][0] = f2tf32(As[(rb + grp)     * LDA + k0 + qid]);
                a[mi][1] = f2tf32(As[(rb + grp + 8) * LDA + k0 + qid]);
                a[mi][2] = f2tf32(As[(rb + grp)     * LDA + k0 + qid + 4]);
                a[mi][3] = f2tf32(As[(rb + grp + 8) * LDA + k0 + qid + 4]);
            }
#pragma unroll
            for (int nt = 0; nt < 8; nt++) {
                const int n0 = wn + (nt << 3);
                uint32_t b0 = f2tf32(Bs[(k0 + qid)     * LDB + n0 + grp]);
                uint32_t b1 = f2tf32(Bs[(k0 + qid + 4) * LDB + n0 + grp]);
#pragma unroll
                for (int mi = 0; mi < 2; mi++) {
                    asm volatile(
                        "mma.sync.aligned.m16n8k8.row.col.f32.tf32.tf32.f32 "
                        "{%0,%1,%2,%3}, {%4,%5,%6,%7}, {%8,%9}, {%0,%1,%2,%3};"
                        : "+f"(acc[mi][nt][0]), "+f"(acc[mi][nt][1]),
                          "+f"(acc[mi][nt][2]), "+f"(acc[mi][nt][3])
                        : "r"(a[mi][0]), "r"(a[mi][1]), "r"(a[mi][2]),
                          "r"(a[mi][3]), "r"(b0), "r"(b1));
                }
            }
        }

        const int khOff = (j == 0) ? 4 : 0;   // H -> slot+4, K -> slot+0
#pragma unroll
        for (int mi = 0; mi < 2; mi++) {
            const int r = row0 + wm + (mi << 4) + grp;
#pragma unroll
            for (int nt = 0; nt < 8; nt++) {
                const int col = wn + (nt << 3) + (qid << 1);   // col even
                if (j == 1) {          // Q fp32, pre-scaled
                    if (r < N_NODES)
                        *(float2*)(g_Q + (size_t)r * F + col) =
                            make_float2(acc[mi][nt][0] * SCALE_INV,
                                        acc[mi][nt][1] * SCALE_INV);
                    if (r + 8 < N_NODES)
                        *(float2*)(g_Q + (size_t)(r + 8) * F + col) =
                            make_float2(acc[mi][nt][2] * SCALE_INV,
                                        acc[mi][nt][3] * SCALE_INV);
                } else {               // H/K fp16 interleaved
                    const int slot = ((col >> 2) << 3) + khOff + (col & 3);
                    if (r < N_NODES)
                        *(__half2*)(g_KH + (size_t)r * 256 + slot) =
                            __floats2half2_rn(acc[mi][nt][0], acc[mi][nt][1]);
                    if (r + 8 < N_NODES)
                        *(__half2*)(g_KH + (size_t)(r + 8) * 256 + slot) =
                            __floats2half2_rn(acc[mi][nt][2], acc[mi][nt][3]);
                }
            }
        }
    }
}

// ---------------------------------------------------------------------------
// Fused attention: ONE warp per dst node (R9 config), ILP-4 batches with
// partitioned warp reduction — one exp per lane per 4-edge batch.
// ---------------------------------------------------------------------------
__device__ __forceinline__ void load_kh(unsigned off,
    float& kx, float& ky, float& kz, float& kw,
    float& hx, float& hy, float& hz, float& hw)
{
    uint4 raw = *(const uint4*)((const char*)g_KH + off);
    float2 f0 = __half22float2(*(__half2*)&raw.x);
    float2 f1 = __half22float2(*(__half2*)&raw.y);
    float2 f2 = __half22float2(*(__half2*)&raw.z);
    float2 f3 = __half22float2(*(__half2*)&raw.w);
    kx = f0.x; ky = f0.y; kz = f1.x; kw = f1.y;
    hx = f2.x; hy = f2.y; hz = f3.x; hw = f3.y;
}

__global__ __launch_bounds__(256) void fused_attn_kernel(float* __restrict__ out)
{
    int gw = (blockIdx.x * blockDim.x + threadIdx.x) >> 5;   // node id
    if (gw >= N_NODES) return;
    int lane = threadIdx.x & 31;

    int beg = g_rowStart[gw];
    int end = g_rowStart[gw + 1];

    float* orow = out + (size_t)gw * F + lane * 4;
    if (beg == end) {
        *(float4*)orow = make_float4(0.f, 0.f, 0.f, 0.f);
        return;
    }

    float4 q = *(const float4*)(g_Q + (unsigned)(gw * F + lane * 4));

    float ax = 0.f, ay = 0.f, az = 0.f, aw = 0.f;
    float den = 0.f;
    const unsigned lo = (unsigned)(lane << 4);   // byte offset within row (16 B/lane)
    const int g = lane >> 3;                     // lane group 0..3

    for (int chunk = beg; chunk < end; chunk += 32) {
        int idx = chunk + lane;
        int myO = (idx < end) ? __ldg(&g_srcOff[idx]) : 0;
        int m = end - chunk; if (m > 32) m = 32;

        int j = 0;
        for (; j + 4 <= m; j += 4) {
            unsigned o0 = (unsigned)__shfl_sync(0xFFFFFFFFu, myO, j)     + lo;
            unsigned o1 = (unsigned)__shfl_sync(0xFFFFFFFFu, myO, j + 1) + lo;
            unsigned o2 = (unsigned)__shfl_sync(0xFFFFFFFFu, myO, j + 2) + lo;
            unsigned o3 = (unsigned)__shfl_sync(0xFFFFFFFFu, myO, j + 3) + lo;
            float k0x,k0y,k0z,k0w, h0x,h0y,h0z,h0w;
            float k1x,k1y,k1z,k1w, h1x,h1y,h1z,h1w;
            float k2x,k2y,k2z,k2w, h2x,h2y,h2z,h2w;
            float k3x,k3y,k3z,k3w, h3x,h3y,h3z,h3w;
            load_kh(o0, k0x,k0y,k0z,k0w, h0x,h0y,h0z,h0w);
            load_kh(o1, k1x,k1y,k1z,k1w, h1x,h1y,h1z,h1w);
            load_kh(o2, k2x,k2y,k2z,k2w, h2x,h2y,h2z,h2w);
            load_kh(o3, k3x,k3y,k3z,k3w, h3x,h3y,h3z,h3w);

            float v0 = q.x*k0x + q.y*k0y + q.z*k0z + q.w*k0w;
            float v1 = q.x*k1x + q.y*k1y + q.z*k1z + q.w*k1w;
            float v2 = q.x*k2x + q.y*k2y + q.z*k2z + q.w*k2w;
            float v3 = q.x*k3x + q.y*k3y + q.z*k3z + q.w*k3w;

            // partitioned reduction: levels 16,8 on all four
            v0 += __shfl_xor_sync(0xFFFFFFFFu, v0, 16);
            v1 += __shfl_xor_sync(0xFFFFFFFFu, v1, 16);
            v2 += __shfl_xor_sync(0xFFFFFFFFu, v2, 16);
            v3 += __shfl_xor_sync(0xFFFFFFFFu, v3, 16);
            v0 += __shfl_xor_sync(0xFFFFFFFFu, v0, 8);
            v1 += __shfl_xor_sync(0xFFFFFFFFu, v1, 8);
            v2 += __shfl_xor_sync(0xFFFFFFFFu, v2, 8);
            v3 += __shfl_xor_sync(0xFFFFFFFFu, v3, 8);
            // each 8-lane group takes one edge's partial (xor 4,2,1 in-group)
            float x = v0;
            x = (g == 1) ? v1 : x;
            x = (g == 2) ? v2 : x;
            x = (g == 3) ? v3 : x;
            x += __shfl_xor_sync(0xFFFFFFFFu, x, 4);
            x += __shfl_xor_sync(0xFFFFFFFFu, x, 2);
            x += __shfl_xor_sync(0xFFFFFFFFu, x, 1);
            float y = __expf(x);                     // ONE exp per lane
            float e0 = __shfl_sync(0xFFFFFFFFu, y, 0);
            float e1 = __shfl_sync(0xFFFFFFFFu, y, 8);
            float e2 = __shfl_sync(0xFFFFFFFFu, y, 16);
            float e3 = __shfl_sync(0xFFFFFFFFu, y, 24);

            den += (e0 + e1) + (e2 + e3);
            ax += e0*h0x + e1*h1x + e2*h2x + e3*h3x;
            ay += e0*h0y + e1*h1y + e2*h2y + e3*h3y;
            az += e0*h0z + e1*h1z + e2*h2z + e3*h3z;
            aw += e0*h0w + e1*h1w + e2*h2w + e3*h3w;
        }
        for (; j < m; j++) {
            unsigned o0 = (unsigned)__shfl_sync(0xFFFFFFFFu, myO, j) + lo;
            float kx,ky,kz,kw, hx,hy,hz,hw;
            load_kh(o0, kx,ky,kz,kw, hx,hy,hz,hw);
            float v0 = q.x*kx + q.y*ky + q.z*kz + q.w*kw;
#pragma unroll
            for (int o = 16; o > 0; o >>= 1)
                v0 += __shfl_xor_sync(0xFFFFFFFFu, v0, o);
            float e0 = __expf(v0);
            den += e0;
            ax += e0*hx; ay += e0*hy; az += e0*hz; aw += e0*hw;
        }
    }

    float inv = 1.0f / den;
    *(float4*)orow = make_float4(ax * inv, ay * inv, az * inv, aw * inv);
}

// ---------------------------------------------------------------------------
// Inputs: 0 feat, 1 loc, 2 W_fc, 3 Wq, 4 Wk, 5 Wq2, 6 Wk2, 7 G_w, 8 embed,
// 9 boundaries, 10 src, 11 dst, 12 inter_ids  (e2 branch is dead code)
// ---------------------------------------------------------------------------
extern "C" void kernel_launch(void* const* d_in, const int* in_sizes, int n_in,
                              void* d_out, int out_size)
{
    const float* feat = (const float*)d_in[0];
    const float* Wfc  = (const float*)d_in[2];
    const float* Wq   = (const float*)d_in[3];
    const float* Wk   = (const float*)d_in[4];
    const int*   src  = (const int*)d_in[10];
    const int*   dst  = (const int*)d_in[11];
    float* out = (float*)d_out;

    static cudaStream_t s2 = nullptr;
    static cudaEvent_t evFork = nullptr, evJoin = nullptr;
    if (!s2) {
        cudaFuncSetAttribute(gemm3_tf32_kernel,
                             cudaFuncAttributeMaxDynamicSharedMemorySize,
                             SMEM_BYTES);
        cudaStreamCreateWithFlags(&s2, cudaStreamNonBlocking);
        cudaEventCreateWithFlags(&evFork, cudaEventDisableTiming);
        cudaEventCreateWithFlags(&evJoin, cudaEventDisableTiming);
    }

    // fork: CSR build on s2, GEMM on the main (capture) stream
    cudaEventRecord(evFork, 0);
    cudaStreamWaitEvent(s2, evFork, 0);

    {   // --- s2: CSR build (rank-based, atomic-free scatter) ---
        int t4 = (N_EDGES + 3) / 4;
        hist_kernel<<<(t4 + 255) / 256, 256, 0, s2>>>(dst);
        scan1_kernel<<<NBLK, 256, 0, s2>>>();
        scan23_kernel<<<NBLK, 256, 0, s2>>>();
        scatter_kernel<<<(t4 + 255) / 256, 256, 0, s2>>>(src, dst);
        cudaEventRecord(evJoin, s2);
    }

    // --- main stream: H, Q, K GEMMs ---
    gemm3_tf32_kernel<<<(N_NODES + 127) / 128, 256, SMEM_BYTES>>>(
        feat, Wfc, Wq, Wk);

    // join, then fused attention (1 warp per node)
    cudaStreamWaitEvent(0, evJoin, 0);
    fused_attn_kernel<<<(N_NODES * 32 + 255) / 256, 256>>>(out);
}